// round 14
// baseline (speedup 1.0000x reference)
#include <cuda_runtime.h>
#include <cuda_fp16.h>
#include <cstdint>

#define NN 10000
#define TM 80             // rows per CTA; 125 * 80 = 10000 exactly
#define NCTA 125
#define NTHR 640          // 20 warps
#define EE 320000
#define CC 256
#define KK 512            // B row width (k): [Wn | Wo]
#define LL 3
#define DD 20
#define GAMMA 0.705078125f       // 0.125 / interval^2, interval = 8/19
#define KAF_C1 0.59375f          // 2*gamma*interval
#define KAF_Q  0.778800783f      // exp(-0.25)

// ---------------- scratch (device globals) ----------------
__device__ int   g_deg[NN];
__device__ int   g_off[NN + 1];
__device__ int   g_cursor[NN];
__device__ int   g_slot[EE];
__device__ float g_sea0[NN];
__device__ float g_sea1[NN];
__device__ float g_inv[NN];
__device__ float g_sc0[NN];
__device__ float g_sc1[NN];
// Ping-pong h matrices, fp16 [NN][256]
__device__ __align__(16) __half gH0[NN * CC];
__device__ __align__(16) __half gH1[NN * CC];
// B [l][n_out(256)][k(512)]: k<256 -> neigh_w[k][n], k>=256 -> node_w[k-256][n]
__device__ __align__(16) __half gB[LL * CC * KK];

// ---------------- setup kernels (R8 versions) ----------------
__global__ void k_zero() {
    int i = blockIdx.x * blockDim.x + threadIdx.x;
    if (i < NN) { g_deg[i] = 0; g_cursor[i] = 0; g_sea0[i] = 0.f; g_sea1[i] = 0.f; }
}

__global__ void k_count(const int* __restrict__ ei, const float* __restrict__ ea) {
    int e = blockIdx.x * blockDim.x + threadIdx.x;
    if (e < EE) {
        int dst = ei[EE + e];
        atomicAdd(&g_deg[dst], 1);
        atomicAdd(&g_sea0[dst], ea[2 * e]);
        atomicAdd(&g_sea1[dst], ea[2 * e + 1]);
    }
}

__global__ void k_scan() {
    __shared__ int sh[1024];
    int t = threadIdx.x;
    int loc[10], dv[10];
    int tot = 0;
    #pragma unroll
    for (int j = 0; j < 10; j++) {
        int idx = t * 10 + j;
        int v = (idx < NN) ? g_deg[idx] : 0;
        dv[j] = v;
        loc[j] = tot;
        tot += v;
    }
    sh[t] = tot;
    __syncthreads();
    int sum = tot;
    #pragma unroll
    for (int s = 1; s < 1024; s <<= 1) {
        int u = (t >= s) ? sh[t - s] : 0;
        __syncthreads();
        sum += u;
        sh[t] = sum;
        __syncthreads();
    }
    int base = sum - tot;
    #pragma unroll
    for (int j = 0; j < 10; j++) {
        int idx = t * 10 + j;
        if (idx < NN) {
            g_off[idx] = base + loc[j];
            float inv = (dv[j] > 0) ? 1.0f / (float)dv[j] : 0.0f;
            g_inv[idx] = inv;
            g_sc0[idx] = g_sea0[idx] * inv;
            g_sc1[idx] = g_sea1[idx] * inv;
        }
    }
    if (t == 1023) g_off[NN] = sum;
}

__global__ void k_scatter(const int* __restrict__ ei) {
    int e = blockIdx.x * blockDim.x + threadIdx.x;
    if (e < EE) {
        int src = ei[e];
        int dst = ei[EE + e];
        int pos = g_off[dst] + atomicAdd(&g_cursor[dst], 1);
        g_slot[pos] = src;
    }
}

__global__ void k_split_x(const float* __restrict__ x) {
    int i = blockIdx.x * blockDim.x + threadIdx.x;
    if (i < NN * CC) gH0[i] = __float2half_rn(x[i]);
}

__global__ void k_prep_B(const float* __restrict__ nw, const float* __restrict__ ow) {
    int i = blockIdx.x * blockDim.x + threadIdx.x;
    if (i < LL * CC * KK) {
        int l = i / (CC * KK);
        int r = i - l * CC * KK;
        int n = r >> 9, k = r & 511;
        float v = (k < 256) ? nw[l * CC * CC + k * CC + n]
                            : ow[l * CC * CC + (k - 256) * CC + n];
        gB[i] = __float2half_rn(v);
    }
}

// ---------------- helpers ----------------
#define SW128(x) ((x) ^ (((x) >> 3) & 0x70))

__device__ __forceinline__ uint32_t s2u(const void* p) {
    uint32_t a;
    asm("{ .reg .u64 t; cvta.to.shared.u64 t, %1; cvt.u32.u64 %0, t; }" : "=r"(a) : "l"(p));
    return a;
}

__device__ __forceinline__ void cpa16(uint32_t saddr, const void* gaddr) {
    asm volatile("cp.async.cg.shared.global [%0], [%1], 16;" :: "r"(saddr), "l"(gaddr));
}

__device__ __forceinline__ void ldsm_x4(uint32_t& r0, uint32_t& r1, uint32_t& r2, uint32_t& r3,
                                        uint32_t addr) {
    asm volatile("ldmatrix.sync.aligned.m8n8.x4.shared.b16 {%0,%1,%2,%3}, [%4];"
                 : "=r"(r0), "=r"(r1), "=r"(r2), "=r"(r3) : "r"(addr));
}

__device__ __forceinline__ void mma16816(float* c, const uint32_t* a, const uint32_t* b) {
    asm volatile(
        "mma.sync.aligned.m16n8k16.row.col.f32.f16.f16.f32 "
        "{%0,%1,%2,%3}, {%4,%5,%6,%7}, {%8,%9}, {%0,%1,%2,%3};"
        : "+f"(c[0]), "+f"(c[1]), "+f"(c[2]), "+f"(c[3])
        : "r"(a[0]), "r"(a[1]), "r"(a[2]), "r"(a[3]), "r"(b[0]), "r"(b[1]));
}

__device__ __forceinline__ float kaf_eval(float s, const float* a) {
    float u = s + 4.0f;
    float K = __expf(-GAMMA * u * u);
    float r = __expf(KAF_C1 * u - 0.125f);
    float t = 0.f;
    #pragma unroll
    for (int d = 0; d < DD; d++) { t += a[d] * K; K *= r; r *= KAF_Q; }
    return t;
}

__device__ __forceinline__ void addh8(float* acc, uint4 v) {
    uint32_t w[4] = {v.x, v.y, v.z, v.w};
    #pragma unroll
    for (int u = 0; u < 4; u++) {
        __half2 h = *reinterpret_cast<__half2*>(&w[u]);
        float2 f = __half22float2(h);
        acc[2 * u] += f.x;
        acc[2 * u + 1] += f.y;
    }
}

// ---------------- fused layer kernel ----------------
// SMEM layout
#define AGG_CH 10240                    // one agg chunk: 80 rows x 128 B
#define OFF_AGG 0                       // 4 chunks = 40960
#define OFF_B 40960                     // 2 x 32768 = 65536
#define OFF_H 106496                    // 2 x 10240 = 20480
#define OFF_P 126976                    // 5888 floats = 23552
#define SMEM_TOTAL 150528

__device__ __forceinline__ void issue_chunk(uint32_t ub, const __half* H, const __half* Bl,
                                            int m0, int ch, int tid) {
    uint32_t uB = ub + OFF_B + (uint32_t)(ch & 1) * 32768u;
    #pragma unroll
    for (int it = 0; it < 4; it++) {
        int i = tid + it * NTHR;
        if (i < 2048) {
            int r = i >> 3, c = i & 7;
            cpa16(uB + SW128((uint32_t)(r * 128 + c * 16)), &Bl[r * KK + ch * 64 + c * 8]);
        }
    }
    if (ch >= 4) {
        uint32_t uH = ub + OFF_H + (uint32_t)(ch & 1) * AGG_CH;
        int r = tid >> 3, c = tid & 7;   // 640 = 80*8 exactly
        cpa16(uH + SW128((uint32_t)(r * 128 + c * 16)), &H[(m0 + r) * CC + (ch - 4) * 64 + c * 8]);
    }
}

__global__ __launch_bounds__(NTHR, 1) void k_layer(const __half* __restrict__ H,
                                                   __half* __restrict__ HN,
                                                   const float* __restrict__ ew,
                                                   const float* __restrict__ bias,
                                                   const float* __restrict__ alpha,
                                                   const __half* __restrict__ Bl,
                                                   float* __restrict__ out, int last) {
    extern __shared__ char smem[];
    uint32_t ub = s2u(smem);
    float* sP = (float*)(smem + OFF_P);

    int tid = threadIdx.x, wid = tid >> 5, lid = tid & 31;
    int m0 = blockIdx.x * TM;
    int warp_m = (wid % 5) * 16;        // 5 m-positions x 16 rows
    int warp_n = (wid / 5) * 64;        // 4 n-positions x 64 cols
    int g = lid >> 3, rid = lid & 7;

    // prefetch B chunk 0 (independent of gather)
    issue_chunk(ub, H, Bl, m0, 0, tid);
    asm volatile("cp.async.commit_group;");

    // stage epilogue params
    if (tid < 256) {
        sP[tid] = ew[tid];
        sP[256 + tid] = ew[CC + tid];
        sP[512 + tid] = bias[tid];
    }
    for (int i = tid; i < 256 * DD; i += NTHR)
        sP[768 + i] = alpha[i];

    // ---- gather phase: 20 warps x 4 rows, agg -> swizzled SMEM A tiles ----
    const uint32_t* hv = (const uint32_t*)H;   // row stride 128 uints
    int col4 = lid * 4;
    #pragma unroll
    for (int j = 0; j < 4; j++) {
        int rl = wid * 4 + j;
        int row = m0 + rl;
        float acc8[8];
        #pragma unroll
        for (int k = 0; k < 8; k++) acc8[k] = 0.f;
        int o0 = g_off[row], o1 = g_off[row + 1];
        int e = o0;
        for (; e + 8 <= o1; e += 8) {
            int s[8];
            #pragma unroll
            for (int jj = 0; jj < 8; jj++) s[jj] = g_slot[e + jj];
            uint4 v[8];
            #pragma unroll
            for (int jj = 0; jj < 8; jj++) v[jj] = *(const uint4*)&hv[s[jj] * 128 + col4];
            #pragma unroll
            for (int jj = 0; jj < 8; jj++) addh8(acc8, v[jj]);
        }
        for (; e < o1; e++)
            addh8(acc8, *(const uint4*)&hv[g_slot[e] * 128 + col4]);

        float inv = g_inv[row];
        uint32_t pk[4];
        #pragma unroll
        for (int u = 0; u < 4; u++) {
            __half h0 = __float2half_rn(acc8[2 * u] * inv);
            __half h1 = __float2half_rn(acc8[2 * u + 1] * inv);
            pk[u] = ((uint32_t)*(uint16_t*)&h1 << 16) | *(uint16_t*)&h0;
        }
        uint32_t off = OFF_AGG + (uint32_t)(lid >> 3) * AGG_CH
                     + SW128((uint32_t)(rl * 128 + (lid & 7) * 16));
        *(uint4*)(smem + off) = make_uint4(pk[0], pk[1], pk[2], pk[3]);
    }
    __syncthreads();   // agg tiles + params visible

    // ---- mainloop: K = 512 in 8 chunks; 0-3 A from agg smem, 4-7 A = h streamed ----
    float acc[8][4];
    #pragma unroll
    for (int n = 0; n < 8; n++)
        #pragma unroll
        for (int q = 0; q < 4; q++) acc[n][q] = 0.f;

    for (int ch = 0; ch < 8; ch++) {
        if (ch < 7) {
            issue_chunk(ub, H, Bl, m0, ch + 1, tid);
            asm volatile("cp.async.commit_group;");
            asm volatile("cp.async.wait_group 1;");
        } else {
            asm volatile("cp.async.wait_group 0;");
        }
        __syncthreads();

        uint32_t uB = ub + OFF_B + (uint32_t)(ch & 1) * 32768u;
        uint32_t uA = (ch < 4) ? ub + OFF_AGG + (uint32_t)ch * AGG_CH
                               : ub + OFF_H + (uint32_t)(ch & 1) * AGG_CH;

        #pragma unroll
        for (int ks = 0; ks < 4; ks++) {
            int kc2 = ks * 2;
            uint32_t b[8][2];
            #pragma unroll
            for (int p = 0; p < 4; p++) {
                int rowb = warp_n + p * 16 + ((g >> 1) ? 8 : 0) + rid;
                int chunk = kc2 + (g & 1);
                ldsm_x4(b[2 * p][0], b[2 * p][1], b[2 * p + 1][0], b[2 * p + 1][1],
                        uB + SW128((uint32_t)(rowb * 128 + chunk * 16)));
            }
            uint32_t a[4];
            {
                int rowa = warp_m + ((g & 1) ? 8 : 0) + rid;
                int chunk = kc2 + (g >> 1);
                ldsm_x4(a[0], a[1], a[2], a[3],
                        uA + SW128((uint32_t)(rowa * 128 + chunk * 16)));
            }
            #pragma unroll
            for (int n = 0; n < 8; n++)
                mma16816(acc[n], a, b[n]);
        }
        __syncthreads();
    }

    // ---- epilogue: rank2 + bias + KAF -> next h (or out) ----
    int qm = lid >> 2, qn = (lid & 3) * 2;
    uint32_t* ghi = (uint32_t*)HN;
    #pragma unroll
    for (int rr = 0; rr < 2; rr++) {
        int row = m0 + warp_m + qm + rr * 8;
        float sc0 = g_sc0[row], sc1 = g_sc1[row];
        #pragma unroll
        for (int n = 0; n < 8; n++) {
            int col = warp_n + n * 8 + qn;
            float s0 = acc[n][rr * 2]     + sc0 * sP[col]     + sc1 * sP[256 + col]     + sP[512 + col];
            float s1 = acc[n][rr * 2 + 1] + sc0 * sP[col + 1] + sc1 * sP[256 + col + 1] + sP[512 + col + 1];
            float r0 = kaf_eval(s0, &sP[768 + col * DD]);
            float r1 = kaf_eval(s1, &sP[768 + (col + 1) * DD]);
            if (last) {
                *(float2*)&out[row * CC + col] = make_float2(r0, r1);
            } else {
                __half h0 = __float2half_rn(r0), h1 = __float2half_rn(r1);
                ghi[row * 128 + (col >> 1)] =
                    ((uint32_t)*(uint16_t*)&h1 << 16) | *(uint16_t*)&h0;
            }
        }
    }
}

// ---------------- launch ----------------
static cudaStream_t g_s2 = nullptr;
static cudaEvent_t g_evF = nullptr, g_evJ = nullptr;

extern "C" void kernel_launch(void* const* d_in, const int* in_sizes, int n_in,
                              void* d_out, int out_size) {
    const float* x       = (const float*)d_in[0];
    const int*   ei      = (const int*)d_in[1];
    const float* ea      = (const float*)d_in[2];
    const float* node_w  = (const float*)d_in[3];
    const float* edge_w  = (const float*)d_in[4];
    const float* neigh_w = (const float*)d_in[5];
    const float* bias    = (const float*)d_in[6];
    const float* alpha   = (const float*)d_in[7];
    float* out = (float*)d_out;

    if (!g_s2) {
        cudaStreamCreateWithFlags(&g_s2, cudaStreamNonBlocking);
        cudaEventCreateWithFlags(&g_evF, cudaEventDisableTiming);
        cudaEventCreateWithFlags(&g_evJ, cudaEventDisableTiming);
        cudaFuncSetAttribute(k_layer, cudaFuncAttributeMaxDynamicSharedMemorySize, SMEM_TOTAL);
    }

    __half *h0, *h1, *bb;
    cudaGetSymbolAddress((void**)&h0, gH0);
    cudaGetSymbolAddress((void**)&h1, gH1);
    cudaGetSymbolAddress((void**)&bb, gB);
    __half* HB[2] = {h0, h1};

    // fork: CSR chain on side stream
    cudaEventRecord(g_evF, 0);
    cudaStreamWaitEvent(g_s2, g_evF, 0);
    k_zero<<<(NN + 255) / 256, 256, 0, g_s2>>>();
    k_count<<<(EE + 255) / 256, 256, 0, g_s2>>>(ei, ea);
    k_scan<<<1, 1024, 0, g_s2>>>();
    k_scatter<<<(EE + 255) / 256, 256, 0, g_s2>>>(ei);
    cudaEventRecord(g_evJ, g_s2);

    // main: dense prep
    k_split_x<<<(NN * CC + 255) / 256, 256>>>(x);
    k_prep_B<<<(LL * CC * KK + 255) / 256, 256>>>(neigh_w, node_w);
    cudaStreamWaitEvent(0, g_evJ, 0);

    for (int l = 0; l < LL; l++) {
        int b = l & 1;
        k_layer<<<NCTA, NTHR, SMEM_TOTAL>>>(HB[b], HB[b ^ 1],
                                            edge_w + l * 2 * CC, bias + l * CC,
                                            alpha + l * CC * DD, bb + l * CC * KK,
                                            out, (l == LL - 1) ? 1 : 0);
    }
}

// round 16
// speedup vs baseline: 1.4382x; 1.4382x over previous
#include <cuda_runtime.h>
#include <cuda_fp16.h>
#include <cstdint>

#define NN 10000
#define MPAD 10112        // 79 * 128
#define NT 79
#define EE 320000
#define CC 256
#define KK 512            // GEMM K dim: [agg | h]
#define LL 3
#define DD 20
#define GAMMA 0.705078125f       // 0.125 / interval^2, interval = 8/19
#define KAF_C1 0.59375f          // 2*gamma*interval
#define KAF_Q  0.778800783f      // exp(-0.25)

// ---------------- scratch (device globals) ----------------
__device__ int    g_deg[NN];
__device__ int    g_off[NN + 1];
__device__ int    g_cursor[NN];
__device__ int    g_slot[EE];
__device__ float2 g_ea[EE];            // edge attrs in CSR-slot order
__device__ float  g_inv[NN];
__device__ float  g_sc0[NN];
__device__ float  g_sc1[NN];
// Ping-pong A matrices (fp16). Row layout [KK]: cols 0..255 = agg, cols 256..511 = h
__device__ __align__(16) __half gA0[MPAD * KK];
__device__ __align__(16) __half gA1[MPAD * KK];
// B [l][n_out(256)][k(512)]: k<256 -> neigh_w[k][n], k>=256 -> node_w[k-256][n]
__device__ __align__(16) __half gB[LL * CC * KK];

// ---------------- setup kernels ----------------
__global__ void k_zero() {
    int i = blockIdx.x * blockDim.x + threadIdx.x;
    if (i < NN) { g_deg[i] = 0; g_cursor[i] = 0; }
}

__global__ void k_count(const int* __restrict__ ei) {
    int e = blockIdx.x * blockDim.x + threadIdx.x;
    if (e < EE) atomicAdd(&g_deg[ei[EE + e]], 1);
}

// scan + inv fused
__global__ void k_scan() {
    __shared__ int sh[1024];
    int t = threadIdx.x;
    int loc[10], dv[10];
    int tot = 0;
    #pragma unroll
    for (int j = 0; j < 10; j++) {
        int idx = t * 10 + j;
        int v = (idx < NN) ? g_deg[idx] : 0;
        dv[j] = v;
        loc[j] = tot;
        tot += v;
    }
    sh[t] = tot;
    __syncthreads();
    int sum = tot;
    #pragma unroll
    for (int s = 1; s < 1024; s <<= 1) {
        int u = (t >= s) ? sh[t - s] : 0;
        __syncthreads();
        sum += u;
        sh[t] = sum;
        __syncthreads();
    }
    int base = sum - tot;
    #pragma unroll
    for (int j = 0; j < 10; j++) {
        int idx = t * 10 + j;
        if (idx < NN) {
            g_off[idx] = base + loc[j];
            g_inv[idx] = (dv[j] > 0) ? 1.0f / (float)dv[j] : 0.0f;
        }
    }
    if (t == 1023) g_off[NN] = sum;
}

__global__ void k_scatter(const int* __restrict__ ei, const float* __restrict__ ea) {
    int e = blockIdx.x * blockDim.x + threadIdx.x;
    if (e < EE) {
        int src = ei[e];
        int dst = ei[EE + e];
        int pos = g_off[dst] + atomicAdd(&g_cursor[dst], 1);
        g_slot[pos] = src;
        g_ea[pos] = make_float2(ea[2 * e], ea[2 * e + 1]);
    }
}

// x -> h part (cols 256..511) of A buffer 0
__global__ void k_split_x(const float* __restrict__ x) {
    int i = blockIdx.x * blockDim.x + threadIdx.x;
    if (i < NN * CC) {
        int row = i >> 8, col = i & 255;
        gA0[row * KK + 256 + col] = __float2half_rn(x[i]);
    }
}

__global__ void k_prep_B(const float* __restrict__ nw, const float* __restrict__ ow) {
    int i = blockIdx.x * blockDim.x + threadIdx.x;
    if (i < LL * CC * KK) {
        int l = i / (CC * KK);
        int r = i - l * CC * KK;
        int n = r >> 9, k = r & 511;
        float v = (k < 256) ? nw[l * CC * CC + k * CC + n]
                            : ow[l * CC * CC + (k - 256) * CC + n];
        gB[i] = __float2half_rn(v);
    }
}

// ---------------- gather: agg[n] = inv * sum h[src]; layer0 also sums edge attrs ----------------
__device__ __forceinline__ void addh8(float* acc, uint4 v) {
    uint32_t w[4] = {v.x, v.y, v.z, v.w};
    #pragma unroll
    for (int u = 0; u < 4; u++) {
        __half2 h = *reinterpret_cast<__half2*>(&w[u]);
        float2 f = __half22float2(h);
        acc[2 * u] += f.x;
        acc[2 * u + 1] += f.y;
    }
}

__global__ __launch_bounds__(256) void k_gather(const __half* __restrict__ A,
                                                __half* __restrict__ AW, int first) {
    int n = blockIdx.x * 8 + (threadIdx.x >> 5);
    if (n >= NN) return;
    int lane = threadIdx.x & 31;
    int o0 = g_off[n], o1 = g_off[n + 1];
    int col4 = lane * 4;
    const uint32_t* hv = (const uint32_t*)A;

    float acc[8];
    #pragma unroll
    for (int k = 0; k < 8; k++) acc[k] = 0.f;
    float se0 = 0.f, se1 = 0.f;
    bool do_sea = first && (lane == 0);

    int e = o0;
    for (; e + 8 <= o1; e += 8) {
        int s[8];
        #pragma unroll
        for (int j = 0; j < 8; j++) s[j] = g_slot[e + j];
        if (do_sea) {
            #pragma unroll
            for (int j = 0; j < 8; j++) {
                float2 t = g_ea[e + j];
                se0 += t.x; se1 += t.y;
            }
        }
        uint4 v[8];
        #pragma unroll
        for (int j = 0; j < 8; j++) v[j] = *(const uint4*)&hv[s[j] * 256 + 128 + col4];
        #pragma unroll
        for (int j = 0; j < 8; j++) addh8(acc, v[j]);
    }
    for (; e < o1; e++) {
        int s = g_slot[e];
        if (do_sea) {
            float2 t = g_ea[e];
            se0 += t.x; se1 += t.y;
        }
        addh8(acc, *(const uint4*)&hv[s * 256 + 128 + col4]);
    }

    float inv = g_inv[n];
    if (do_sea) {
        g_sc0[n] = se0 * inv;
        g_sc1[n] = se1 * inv;
    }
    uint32_t pk[4];
    #pragma unroll
    for (int u = 0; u < 4; u++) {
        __half h0 = __float2half_rn(acc[2 * u] * inv);
        __half h1 = __float2half_rn(acc[2 * u + 1] * inv);
        pk[u] = ((uint32_t)*(uint16_t*)&h1 << 16) | *(uint16_t*)&h0;
    }
    *(uint4*)&((uint32_t*)AW)[n * 256 + col4] = make_uint4(pk[0], pk[1], pk[2], pk[3]);
}

// ---------------- fused GEMM + rank2 + bias + KAF (byte-identical to R8) ----------------
#define SW128(x) ((x) ^ (((x) >> 3) & 0x70))

__device__ __forceinline__ uint32_t s2u(const void* p) {
    uint32_t a;
    asm("{ .reg .u64 t; cvta.to.shared.u64 t, %1; cvt.u32.u64 %0, t; }" : "=r"(a) : "l"(p));
    return a;
}

__device__ __forceinline__ void cpa16(uint32_t saddr, const void* gaddr) {
    asm volatile("cp.async.cg.shared.global [%0], [%1], 16;" :: "r"(saddr), "l"(gaddr));
}

__device__ __forceinline__ void ldsm_x4(uint32_t& r0, uint32_t& r1, uint32_t& r2, uint32_t& r3,
                                        uint32_t addr) {
    asm volatile("ldmatrix.sync.aligned.m8n8.x4.shared.b16 {%0,%1,%2,%3}, [%4];"
                 : "=r"(r0), "=r"(r1), "=r"(r2), "=r"(r3) : "r"(addr));
}

__device__ __forceinline__ void mma16816(float* c, const uint32_t* a, const uint32_t* b) {
    asm volatile(
        "mma.sync.aligned.m16n8k16.row.col.f32.f16.f16.f32 "
        "{%0,%1,%2,%3}, {%4,%5,%6,%7}, {%8,%9}, {%0,%1,%2,%3};"
        : "+f"(c[0]), "+f"(c[1]), "+f"(c[2]), "+f"(c[3])
        : "r"(a[0]), "r"(a[1]), "r"(a[2]), "r"(a[3]), "r"(b[0]), "r"(b[1]));
}

__device__ __forceinline__ float kaf_eval(float s, const float* a) {
    float u = s + 4.0f;
    float K = __expf(-GAMMA * u * u);
    float r = __expf(KAF_C1 * u - 0.125f);
    float t = 0.f;
    #pragma unroll
    for (int d = 0; d < DD; d++) { t += a[d] * K; K *= r; r *= KAF_Q; }
    return t;
}

#define TB 16384                         // 128 rows x 64 halves x 2B
#define STAGE (2 * TB)                   // A, B
#define SMEM_TOTAL (2 * STAGE)           // 65536

__device__ __forceinline__ void load_chunk(uint32_t st,
                                           const __half* A, const __half* Bl,
                                           int m0, int nb, int kg, int tid) {
    uint32_t uA = st, uB = st + TB;
    #pragma unroll
    for (int it = 0; it < 4; it++) {
        int i = tid + it * 256;
        int r = i >> 3, c = i & 7;
        uint32_t so = SW128((uint32_t)(r * 128 + c * 16));
        cpa16(uA + so, &A[(m0 + r) * KK + kg + c * 8]);
        cpa16(uB + so, &Bl[(nb * 128 + r) * KK + kg + c * 8]);
    }
}

__global__ __launch_bounds__(256) void k_gemm_fused(int layer,
                                                    const __half* __restrict__ A,
                                                    __half* __restrict__ AN,
                                                    const float* __restrict__ ew,
                                                    const float* __restrict__ bias,
                                                    const float* __restrict__ alpha,
                                                    float* __restrict__ out, int last) {
    extern __shared__ char smem[];
    uint32_t ubase = s2u(smem);
    const __half* Bl = gB + layer * CC * KK;

    int tid = threadIdx.x, wid = tid >> 5, lid = tid & 31;
    int m0 = blockIdx.x * 128;
    int nblk = blockIdx.y;
    int c0 = nblk * 128;
    int warp_m = (wid & 3) * 32;
    int warp_n = (wid >> 2) * 64;

    float acc[2][8][4];
    #pragma unroll
    for (int t = 0; t < 2; t++)
        #pragma unroll
        for (int n = 0; n < 8; n++)
            #pragma unroll
            for (int j = 0; j < 4; j++) acc[t][n][j] = 0.f;

    int g = lid >> 3, rid = lid & 7;

    load_chunk(ubase, A, Bl, m0, nblk, 0, tid);
    asm volatile("cp.async.commit_group;");

    for (int ch = 0; ch < 8; ch++) {
        if (ch < 7) {
            load_chunk(ubase + ((ch + 1) & 1) * STAGE, A, Bl, m0, nblk, (ch + 1) * 64, tid);
            asm volatile("cp.async.commit_group;");
            asm volatile("cp.async.wait_group 1;");
        } else {
            asm volatile("cp.async.wait_group 0;");
        }
        __syncthreads();

        uint32_t st = ubase + (ch & 1) * STAGE;
        uint32_t uA = st, uB = st + TB;

        #pragma unroll
        for (int ks = 0; ks < 4; ks++) {
            int kc2 = ks * 2;
            uint32_t b[8][2];
            #pragma unroll
            for (int p = 0; p < 4; p++) {
                int row = warp_n + p * 16 + ((g >> 1) ? 8 : 0) + rid;
                int chunk = kc2 + (g & 1);
                ldsm_x4(b[2 * p][0], b[2 * p][1], b[2 * p + 1][0], b[2 * p + 1][1],
                        uB + SW128((uint32_t)(row * 128 + chunk * 16)));
            }
            uint32_t a[2][4];
            #pragma unroll
            for (int t = 0; t < 2; t++) {
                int row = warp_m + t * 16 + ((g & 1) ? 8 : 0) + rid;
                int chunk = kc2 + (g >> 1);
                ldsm_x4(a[t][0], a[t][1], a[t][2], a[t][3],
                        uA + SW128((uint32_t)(row * 128 + chunk * 16)));
            }
            #pragma unroll
            for (int t = 0; t < 2; t++)
                #pragma unroll
                for (int n = 0; n < 8; n++)
                    mma16816(acc[t][n], a[t], b[n]);
        }
        __syncthreads();
    }

    // stage per-column params AFTER mainloop (R8 layout, reuses tile smem)
    float* sP = (float*)smem;
    for (int i = tid; i < 128; i += 256) {
        int c = c0 + i;
        sP[i] = ew[c];
        sP[128 + i] = ew[CC + c];
        sP[256 + i] = bias[c];
    }
    for (int i = tid; i < 128 * DD; i += 256)
        sP[384 + i] = alpha[c0 * DD + i];
    __syncthreads();

    int qm = lid >> 2, qn = (lid & 3) * 2;
    uint32_t* ghi = (uint32_t*)AN;
    #pragma unroll
    for (int t = 0; t < 2; t++) {
        #pragma unroll
        for (int rr = 0; rr < 2; rr++) {
            int row = m0 + warp_m + t * 16 + qm + rr * 8;
            if (row >= NN) continue;
            float sc0 = g_sc0[row], sc1 = g_sc1[row];
            #pragma unroll
            for (int n = 0; n < 8; n++) {
                int lc = warp_n + n * 8 + qn;
                float s0 = acc[t][n][rr * 2]     + sc0 * sP[lc]     + sc1 * sP[128 + lc]     + sP[256 + lc];
                float s1 = acc[t][n][rr * 2 + 1] + sc0 * sP[lc + 1] + sc1 * sP[128 + lc + 1] + sP[256 + lc + 1];
                float r0 = kaf_eval(s0, &sP[384 + lc * DD]);
                float r1 = kaf_eval(s1, &sP[384 + (lc + 1) * DD]);
                if (last) {
                    *(float2*)&out[row * CC + c0 + lc] = make_float2(r0, r1);
                } else {
                    __half h0 = __float2half_rn(r0), h1 = __float2half_rn(r1);
                    uint32_t phi = ((uint32_t)*(uint16_t*)&h1 << 16) | *(uint16_t*)&h0;
                    ghi[row * 256 + 128 + ((c0 + lc) >> 1)] = phi;
                }
            }
        }
    }
}

// ---------------- launch ----------------
static cudaStream_t g_s2 = nullptr;
static cudaEvent_t g_evF = nullptr, g_evJ = nullptr;

extern "C" void kernel_launch(void* const* d_in, const int* in_sizes, int n_in,
                              void* d_out, int out_size) {
    const float* x       = (const float*)d_in[0];
    const int*   ei      = (const int*)d_in[1];
    const float* ea      = (const float*)d_in[2];
    const float* node_w  = (const float*)d_in[3];
    const float* edge_w  = (const float*)d_in[4];
    const float* neigh_w = (const float*)d_in[5];
    const float* bias    = (const float*)d_in[6];
    const float* alpha   = (const float*)d_in[7];
    float* out = (float*)d_out;

    if (!g_s2) {
        cudaStreamCreateWithFlags(&g_s2, cudaStreamNonBlocking);
        cudaEventCreateWithFlags(&g_evF, cudaEventDisableTiming);
        cudaEventCreateWithFlags(&g_evJ, cudaEventDisableTiming);
        cudaFuncSetAttribute(k_gemm_fused, cudaFuncAttributeMaxDynamicSharedMemorySize, SMEM_TOTAL);
    }

    __half *a0, *a1;
    cudaGetSymbolAddress((void**)&a0, gA0);
    cudaGetSymbolAddress((void**)&a1, gA1);
    __half* AB[2] = {a0, a1};

    // fork: CSR chain on side stream
    cudaEventRecord(g_evF, 0);
    cudaStreamWaitEvent(g_s2, g_evF, 0);
    k_zero<<<(NN + 255) / 256, 256, 0, g_s2>>>();
    k_count<<<(EE + 255) / 256, 256, 0, g_s2>>>(ei);
    k_scan<<<1, 1024, 0, g_s2>>>();
    k_scatter<<<(EE + 255) / 256, 256, 0, g_s2>>>(ei, ea);
    cudaEventRecord(g_evJ, g_s2);

    // main: dense prep
    k_split_x<<<(NN * CC + 255) / 256, 256>>>(x);
    k_prep_B<<<(LL * CC * KK + 255) / 256, 256>>>(neigh_w, node_w);
    cudaStreamWaitEvent(0, g_evJ, 0);

    dim3 gg(NT, 2);
    for (int l = 0; l < LL; l++) {
        int b = l & 1;
        k_gather<<<(NN + 7) / 8, 256>>>(AB[b], AB[b], (l == 0) ? 1 : 0);
        k_gemm_fused<<<gg, 256, SMEM_TOTAL>>>(l, AB[b], AB[b ^ 1],
                                              edge_w + l * 2 * CC, bias + l * CC,
                                              alpha + l * CC * DD, out, (l == LL - 1) ? 1 : 0);
    }
}